// round 6
// baseline (speedup 1.0000x reference)
#include <cuda_runtime.h>
#include <math.h>
#include <stdint.h>
#include <stddef.h>

// DBN beat decoder, persistent-delta chunked Viterbi, fused A-phase.
// tau = 28..109 (82 tempi), S = 5617, B = 4, T = 6000.
#define NI     82
#define TROW   84       // trans_t row stride (i-major), mult of 4
#define LRT    30       // LbufT row stride: LbufT[i*LRT + f]
#define LBSZ   (NI * LRT)
#define FR     84       // Fbuf row stride
#define S_TOT  5617
#define S_PAD  5632
#define T_LEN  6000
#define BATCH  4
#define TPB    1024
#define CHUNK  28
#define NFULL  214      // full chunks cover t = 1..5992
#define NTOPS  2296     // 28*82
#define NMAIN  3321     // states with p >= 28
#define BTH    294      // B threads: 21 j-quads x 14 f-pairs
#define NAM    1890     // A-main tasks (j >= g+1)
#define NAT    406      // A-top tasks (j <= g)

__device__ float g_L[(size_t)BATCH * T_LEN * NI];   // exact L for lazy backtrace

__device__ __forceinline__ int first_of(int j) { return 28 * j + (j * (j - 1)) / 2; }
__device__ __forceinline__ int last_of(int j)  { return first_of(j) + 27 + j; }

__global__ __launch_bounds__(TPB, 1)
void dbn_kernel(const float* __restrict__ logit, float* __restrict__ out)
{
    extern __shared__ char smraw[];
    float* trans_t = (float*)smraw;                 // [84][84] trans_t[i][j]
    float* dbuf    = trans_t + TROW * TROW;         // [2][5632] persistent delta
    float* LbufT   = dbuf + 2 * S_PAD;              // [2][82][30]  L[(buf)][i][f]
    float* Fbuf    = LbufT + 2 * LBSZ;              // [28][84] (16B aligned)
    float* blp     = Fbuf + CHUNK * FR;             // 6000
    float* nlp     = blp + T_LEN;                   // 6000
    float* redv    = nlp + T_LEN;                   // 32
    int*   redi    = (int*)(redv + 32);             // 32
    unsigned* amtask = (unsigned*)(redi + 32);      // 1890
    unsigned* attask = amtask + NAM;                // 406
    unsigned char* isf = (unsigned char*)(attask + NAT);  // 5632

    const int tid = threadIdx.x;
    const int b   = blockIdx.x;
    const float* lg = logit + (size_t)b * T_LEN;
    float* Lg   = g_L + (size_t)b * T_LEN * NI;
    float* outb = out + (size_t)b * T_LEN;

    // ================= setup =================
    if (tid < NI) {               // trans row i = tid (fp64, matches numpy)
        double ti = (double)(28 + tid);
        double sum = 0.0;
        for (int jj = 0; jj < NI; ++jj)
            sum += exp(-100.0 * fabs((double)(28 + jj) / ti - 1.0));
        double ls = log(sum);
        for (int jj = 0; jj < NI; ++jj) {
            double r = -100.0 * fabs((double)(28 + jj) / ti - 1.0);
            trans_t[tid * TROW + jj] = (float)(r - ls);
        }
        trans_t[tid * TROW + 82] = -1e30f;
        trans_t[tid * TROW + 83] = -1e30f;
    }
    for (int s = tid; s < S_PAD; s += TPB) isf[s] = 0;
    for (int t = tid; t < T_LEN; t += TPB) {
        float x  = lg[t];
        float l1 = log1pf(expf(-fabsf(x)));
        blp[t] = fminf(x, 0.0f) - l1;
        nlp[t] = fminf(-x, 0.0f) - l1;
    }
    // task tables: A task (g,j): source s = last_j - g, chain length g
    for (int k = tid; k < NTOPS; k += TPB) {
        int g = k / NI, j = k - g * NI;
        unsigned pk = (unsigned)(last_of(j) - g) | ((unsigned)j << 13) | ((unsigned)g << 20);
        if (j >= g + 1) amtask[81 * g - (g * (g - 1)) / 2 + (j - g - 1)] = pk;
        else           attask[(g * (g + 1)) / 2 + j] = pk;
    }
    __syncthreads();
    if (tid < NI) isf[first_of(tid)] = 1;
    __syncthreads();

    const float logS = logf((float)S_TOT);
    for (int s = tid; s < S_TOT; s += TPB)
        dbuf[s] = (isf[s] ? blp[0] : nlp[0]) - logS;

    // ---- per-thread chunk-invariant constants ----
    // C-top tasks 3*tid+m (task = p*82 + j), plus packed (j,p) for fused A-top ext
    int Cth[3], Cfb[3], Cdn[3], Cpj[3];
#pragma unroll
    for (int m = 0; m < 3; ++m) {
        int task = 3 * tid + m;
        if (task < NTOPS) {
            int p = task / NI, j = task - p * NI;
            Cth[m] = 28 - p; Cfb[m] = (27 - p) * FR + j; Cdn[m] = first_of(j) + p;
            Cpj[m] = j | (p << 7);
        } else { Cth[m] = 28; Cfb[m] = 0; Cdn[m] = 0; Cpj[m] = 127; }
    }
    // C-main (tid >= BTH): 5 states in regs
    int Ms[5];
    if (tid >= BTH) {
#pragma unroll
        for (int m = 0; m < 5; ++m) {
            int kk = 5 * (tid - BTH) + m;
            if (kk < NMAIN) {
                int j = (int)((1.0 + sqrt(8.0 * (double)kk + 1.0)) * 0.5);
                while ((j * (j + 1)) / 2 <= kk) ++j;
                while ((j * (j - 1)) / 2 > kk)  --j;
                int mm = kk - (j * (j - 1)) / 2;
                Ms[m] = first_of(j) + 28 + mm;
            } else Ms[m] = S_PAD - 1;
        }
    }
    // B mapping (tid < BTH): jq = tid/14, f0 = 2*(tid%14)
    const int jq = tid / 14;
    const int f0 = 2 * (tid - 14 * jq);
    __syncthreads();

    // ================= priming: A for chunk 0 from delta0 =================
    {
        const float* npp = nlp + 1;
        float* Lgp = Lg + NI;                 // row t = 1+g
        if (tid >= 79) {
            int base = 2 * (tid - 79);
            unsigned w0 = amtask[base], w1 = amtask[base + 1];
            int s0 = w0 & 0x1FFF, j0 = (w0 >> 13) & 0x7F, g0 = (int)(w0 >> 20);
            int s1 = w1 & 0x1FFF, j1 = (w1 >> 13) & 0x7F, g1 = (int)(w1 >> 20);
            float a0 = dbuf[s0], a1 = dbuf[s1];
            int kmax = g0 > g1 ? g0 : g1;
            for (int k = 0; k < kmax; ++k) {
                float v = npp[k];
                if (k < g0) a0 += v;
                if (k < g1) a1 += v;
            }
            LbufT[j0 * LRT + g0] = a0; Lgp[g0 * NI + j0] = a0;
            LbufT[j1 * LRT + g1] = a1; Lgp[g1 * NI + j1] = a1;
        }
        if (tid < NAT) {
            unsigned w = attask[tid];
            int s = w & 0x1FFF, j = (w >> 13) & 0x7F, g = (int)(w >> 20);
            float a = dbuf[s];
            for (int k = 0; k < g; ++k) a += npp[k];
            LbufT[j * LRT + g] = a; Lgp[g * NI + j] = a;
        }
    }
    __syncthreads();

    // ================= 214 full chunks, 2 barriers each =================
    for (int c = 0; c < NFULL; ++c) {
        const int t0 = 1 + CHUNK * c;
        const float* dprev = dbuf + (c & 1) * S_PAD;
        float*       dnew  = dbuf + ((c + 1) & 1) * S_PAD;
        const float* Lcur  = LbufT + (c & 1) * LBSZ;
        float*       Lnxt  = LbufT + ((c + 1) & 1) * LBSZ;
        const float* np    = nlp + t0;
        const float* np2   = np + CHUNK;
        const bool   prep  = (c + 1 < NFULL);

        // ---- P1: B (tid<294, 4j x 2f) | C-main (tid>=294) ----
        if (tid < BTH) {
            const float4* tc = (const float4*)trans_t + jq;
            const float2* Lp = (const float2*)(Lcur + f0);
            float4 A0 = make_float4(-1e30f, -1e30f, -1e30f, -1e30f);
            float4 A1 = A0;
#pragma unroll 2
            for (int i = 0; i < NI; ++i) {
                float4 tv = tc[i * (TROW / 4)];
                float2 l  = Lp[i * (LRT / 2)];
                A0.x = fmaxf(A0.x, l.x + tv.x); A0.y = fmaxf(A0.y, l.x + tv.y);
                A0.z = fmaxf(A0.z, l.x + tv.z); A0.w = fmaxf(A0.w, l.x + tv.w);
                A1.x = fmaxf(A1.x, l.y + tv.x); A1.y = fmaxf(A1.y, l.y + tv.y);
                A1.z = fmaxf(A1.z, l.y + tv.z); A1.w = fmaxf(A1.w, l.y + tv.w);
            }
            float b0 = blp[t0 + f0], b1 = blp[t0 + f0 + 1];
            *(float4*)(Fbuf + f0 * FR + 4 * jq) =
                make_float4(A0.x + b0, A0.y + b0, A0.z + b0, A0.w + b0);
            *(float4*)(Fbuf + (f0 + 1) * FR + 4 * jq) =
                make_float4(A1.x + b1, A1.y + b1, A1.z + b1, A1.w + b1);
        } else {
            float m0 = dprev[Ms[0] - CHUNK], m1 = dprev[Ms[1] - CHUNK];
            float m2 = dprev[Ms[2] - CHUNK], m3 = dprev[Ms[3] - CHUNK];
            float m4 = dprev[Ms[4] - CHUNK];
#pragma unroll
            for (int k = 0; k < CHUNK; ++k) {
                float v = np[k];
                m0 += v; m1 += v; m2 += v; m3 += v; m4 += v;
            }
            int base = 5 * (tid - BTH);
            if (base     < NMAIN) dnew[Ms[0]] = m0;
            if (base + 1 < NMAIN) dnew[Ms[1]] = m1;
            if (base + 2 < NMAIN) dnew[Ms[2]] = m2;
            if (base + 3 < NMAIN) dnew[Ms[3]] = m3;
            if (base + 4 < NMAIN) dnew[Ms[4]] = m4;
        }
        __syncthreads();

        // ---- P2: C-top (+fused A-top ext) + A-main for next chunk ----
        {
            bool v0 = (3 * tid)     < NTOPS;
            bool v1 = (3 * tid + 1) < NTOPS;
            bool v2 = (3 * tid + 2) < NTOPS;
            float c0 = v0 ? Fbuf[Cfb[0]] : 0.0f;
            float c1 = v1 ? Fbuf[Cfb[1]] : 0.0f;
            float c2 = v2 ? Fbuf[Cfb[2]] : 0.0f;
            int kmin = Cth[0]; if (Cth[1] < kmin) kmin = Cth[1]; if (Cth[2] < kmin) kmin = Cth[2];
#pragma unroll 4
            for (int k = kmin; k < CHUNK; ++k) {
                float v = np[k];
                if (k >= Cth[0]) c0 += v;
                if (k >= Cth[1]) c1 += v;
                if (k >= Cth[2]) c2 += v;
            }
            if (v0) dnew[Cdn[0]] = c0;
            if (v1) dnew[Cdn[1]] = c1;
            if (v2) dnew[Cdn[2]] = c2;

            if (prep) {
                float* Lgn = Lg + (size_t)(t0 + CHUNK) * NI;
                // fused A-top: extend own C-top states (j <= p -> g = 27+j-p)
                int j0 = Cpj[0] & 127, p0 = Cpj[0] >> 7, ge0 = 27 + j0 - p0;
                int j1 = Cpj[1] & 127, p1 = Cpj[1] >> 7, ge1 = 27 + j1 - p1;
                int j2 = Cpj[2] & 127, p2 = Cpj[2] >> 7, ge2 = 27 + j2 - p2;
                bool e0 = ge0 <= 27, e1 = ge1 <= 27, e2 = ge2 <= 27;
                if (e0 || e1 || e2) {
                    int g0 = e0 ? ge0 : 0, g1 = e1 ? ge1 : 0, g2 = e2 ? ge2 : 0;
                    int kmax = g0; if (g1 > kmax) kmax = g1; if (g2 > kmax) kmax = g2;
                    float x0 = c0, x1 = c1, x2 = c2;
                    for (int k = 0; k < kmax; ++k) {
                        float v = np2[k];
                        if (k < g0) x0 += v;
                        if (k < g1) x1 += v;
                        if (k < g2) x2 += v;
                    }
                    if (e0) { Lnxt[j0 * LRT + ge0] = x0; Lgn[ge0 * NI + j0] = x0; }
                    if (e1) { Lnxt[j1 * LRT + ge1] = x1; Lgn[ge1 * NI + j1] = x1; }
                    if (e2) { Lnxt[j2 * LRT + ge2] = x2; Lgn[ge2 * NI + j2] = x2; }
                }
                // A-main: sources are C-main outputs (written in P1)
                if (tid >= 79) {
                    int base = 2 * (tid - 79);
                    unsigned w0 = amtask[base], w1 = amtask[base + 1];
                    int s0 = w0 & 0x1FFF, mj0 = (w0 >> 13) & 0x7F, mg0 = (int)(w0 >> 20);
                    int s1 = w1 & 0x1FFF, mj1 = (w1 >> 13) & 0x7F, mg1 = (int)(w1 >> 20);
                    float a0 = dnew[s0], a1 = dnew[s1];
                    int kmax = mg0 > mg1 ? mg0 : mg1;
                    for (int k = 0; k < kmax; ++k) {
                        float v = np2[k];
                        if (k < mg0) a0 += v;
                        if (k < mg1) a1 += v;
                    }
                    Lnxt[mj0 * LRT + mg0] = a0; Lgn[mg0 * NI + mj0] = a0;
                    Lnxt[mj1 * LRT + mg1] = a1; Lgn[mg1 * NI + mj1] = a1;
                }
            }
        }
        __syncthreads();
    }

    // ================= tail frames t = 5993..5999 =================
    int ping = NFULL & 1;
    for (int t = 1 + CHUNK * NFULL; t < T_LEN; ++t) {
        const float* dprev = dbuf + ping * S_PAD;
        float*       dnew  = dbuf + (ping ^ 1) * S_PAD;
        if (tid < NI) {
            float lv = dprev[last_of(tid)];
            Fbuf[tid] = lv;                       // scratch
            Lg[(size_t)t * NI + tid] = lv;
        }
        __syncthreads();
        if (tid < NI) {
            float m = -1e30f;
            for (int i = 0; i < NI; ++i)
                m = fmaxf(m, Fbuf[i] + trans_t[i * TROW + tid]);
            dnew[first_of(tid)] = m + blp[t];
        } else if (tid >= 128) {
            float nb = nlp[t];
            for (int s = tid - 128; s < S_TOT; s += TPB - 128)
                if (!isf[s]) dnew[s] = dprev[s - 1] + nb;
        }
        __syncthreads();
        ping ^= 1;
    }

    // ================= final argmax (first-max = smallest s) =================
    const float* df = dbuf + ping * S_PAD;
    for (int t = tid; t < T_LEN; t += TPB) outb[t] = 0.0f;

    float bv = -INFINITY; int bs = 0x7fffffff;
    for (int s = tid; s < S_TOT; s += TPB) {
        float v = df[s];
        if (v > bv) { bv = v; bs = s; }
    }
#pragma unroll
    for (int off = 16; off; off >>= 1) {
        float ov = __shfl_xor_sync(0xffffffffu, bv, off);
        int   oi = __shfl_xor_sync(0xffffffffu, bs, off);
        if (ov > bv || (ov == bv && oi < bs)) { bv = ov; bs = oi; }
    }
    if ((tid & 31) == 0) { redv[tid >> 5] = bv; redi[tid >> 5] = bs; }
    __syncthreads();

    // ================= warp-cooperative lazy backtrace =================
    if (tid < 32) {
        bv = redv[tid]; bs = redi[tid];
#pragma unroll
        for (int off = 16; off; off >>= 1) {
            float ov = __shfl_xor_sync(0xffffffffu, bv, off);
            int   oi = __shfl_xor_sync(0xffffffffu, bs, off);
            if (ov > bv || (ov == bv && oi < bs)) { bv = ov; bs = oi; }
        }
        int lo = 0, hi = 81;
        while (lo < hi) { int mid = (lo + hi + 1) >> 1; if (first_of(mid) <= bs) lo = mid; else hi = mid - 1; }
        int j   = lo;
        int pos = bs - first_of(j);
        int t   = T_LEN - 1;
        const int lane = tid;

        while (true) {
            int te = t - pos;
            if (te < 0) break;
            if (lane == 0) {
                float x  = lg[te];
                float sg = 1.0f / (1.0f + expf(-x));
                if (sg >= 0.05f) outb[te] = 1.0f;
            }
            if (te == 0) break;
            const float* Lr = Lg + (size_t)te * NI;
            float best = -INFINITY; int bi = 0x7fffffff;
            for (int i = lane; i < NI; i += 32) {
                float cc = Lr[i] + trans_t[i * TROW + j];
                if (cc > best) { best = cc; bi = i; }
            }
#pragma unroll
            for (int off = 16; off; off >>= 1) {
                float ov = __shfl_xor_sync(0xffffffffu, best, off);
                int   oi = __shfl_xor_sync(0xffffffffu, bi,   off);
                if (ov > best || (ov == best && oi < bi)) { best = ov; bi = oi; }
            }
            j   = bi;
            pos = 27 + j;
            t   = te - 1;
        }
    }
}

extern "C" void kernel_launch(void* const* d_in, const int* in_sizes, int n_in,
                              void* d_out, int out_size)
{
    (void)in_sizes; (void)n_in; (void)out_size;
    const float* logit = (const float*)d_in[0];
    float* out = (float*)d_out;

    const size_t smem = (size_t)(TROW * TROW + 2 * S_PAD + 2 * LBSZ + CHUNK * FR
                                 + 2 * T_LEN + 32) * 4
                      + 32 * 4 + (size_t)(NAM + NAT) * 4 + S_PAD;
    cudaFuncSetAttribute(dbn_kernel,
                         cudaFuncAttributeMaxDynamicSharedMemorySize, (int)smem);
    dbn_kernel<<<BATCH, TPB, smem>>>(logit, out);
}

// round 7
// speedup vs baseline: 1.1917x; 1.1917x over previous
#include <cuda_runtime.h>
#include <math.h>
#include <stdint.h>
#include <stddef.h>

// DBN beat decoder, persistent-delta chunked Viterbi, i-split B phase.
// tau = 28..109 (82 tempi), S = 5617, B = 4, T = 6000.
#define NI     82
#define TROW   84       // trans_t row stride (i-major), mult of 4
#define LR     85       // Lbuf row stride (odd -> conflict-free f-strided access)
#define FR     84       // Pbuf row stride
#define S_TOT  5617
#define S_PAD  5632
#define T_LEN  6000
#define BATCH  4
#define TPB    1024
#define CHUNK  28
#define NFULL  214      // full chunks cover t = 1..5992
#define NTOPS  2296     // 28*82
#define NMAIN  3321     // states with p >= 28
#define BTH    588      // B threads: 2 i-halves x 21 j-quads x 14 f-pairs
#define CIDX_N 3488     // 436 C-main threads x 8 states

__device__ float g_L[(size_t)BATCH * T_LEN * NI];   // exact L for lazy backtrace

__device__ __forceinline__ int first_of(int j) { return 28 * j + (j * (j - 1)) / 2; }
__device__ __forceinline__ int last_of(int j)  { return first_of(j) + 27 + j; }

__global__ __launch_bounds__(TPB, 1)
void dbn_kernel(const float* __restrict__ logit, float* __restrict__ out)
{
    extern __shared__ char smraw[];
    float* trans_t = (float*)smraw;                 // [84][84] trans_t[i][j]
    float* dbuf    = trans_t + TROW * TROW;         // [2][5632] persistent delta
    float* Lbuf    = dbuf + 2 * S_PAD;              // [28][85]
    float* Pbuf    = Lbuf + CHUNK * LR;             // [2][28][84] B partial maxes
    float* blp     = Pbuf + 2 * CHUNK * FR;         // 6000
    float* nlp     = blp + T_LEN;                   // 6000 (16B aligned)
    float* redv    = nlp + T_LEN;                   // 32
    int*   redi    = (int*)(redv + 32);             // 32
    int*   cidx    = redi + 32;                     // 3488
    unsigned char* isf = (unsigned char*)(cidx + CIDX_N);  // 5632

    const int tid = threadIdx.x;
    const int b   = blockIdx.x;
    const float* lg = logit + (size_t)b * T_LEN;
    float* Lg   = g_L + (size_t)b * T_LEN * NI;
    float* outb = out + (size_t)b * T_LEN;

    // ================= setup =================
    if (tid < NI) {               // trans row i = tid (fp64, matches numpy)
        double ti = (double)(28 + tid);
        double sum = 0.0;
        for (int jj = 0; jj < NI; ++jj)
            sum += exp(-100.0 * fabs((double)(28 + jj) / ti - 1.0));
        double ls = log(sum);
        for (int jj = 0; jj < NI; ++jj) {
            double r = -100.0 * fabs((double)(28 + jj) / ti - 1.0);
            trans_t[tid * TROW + jj] = (float)(r - ls);
        }
        trans_t[tid * TROW + 82] = -1e30f;
        trans_t[tid * TROW + 83] = -1e30f;
    }
    for (int s = tid; s < S_PAD; s += TPB) isf[s] = 0;
    for (int t = tid; t < T_LEN; t += TPB) {
        float x  = lg[t];
        float l1 = log1pf(expf(-fabsf(x)));
        blp[t] = fminf(x, 0.0f) - l1;
        nlp[t] = fminf(-x, 0.0f) - l1;
    }
    // cidx: main-state ids (p >= 28); block j contributes j states at offset j(j-1)/2
    for (int k = tid; k < CIDX_N; k += TPB) {
        if (k < NMAIN) {
            int j = (int)((1.0 + sqrt(8.0 * (double)k + 1.0)) * 0.5);
            while ((j * (j + 1)) / 2 <= k) ++j;
            while ((j * (j - 1)) / 2 > k)  --j;
            int m = k - (j * (j - 1)) / 2;
            cidx[k] = first_of(j) + 28 + m;
        } else cidx[k] = S_PAD - 1;
    }
    __syncthreads();
    if (tid < NI) isf[first_of(tid)] = 1;
    __syncthreads();

    const float logS = logf((float)S_TOT);
    for (int s = tid; s < S_TOT; s += TPB)
        dbuf[s] = (isf[s] ? blp[0] : nlp[0]) - logS;

    // ---- per-thread chunk-invariant constants ----
    // Phase A: tasks 3*tid+m (task = g*82 + j)
    int Ag[3], Aoff[3], Alb[3];
#pragma unroll
    for (int m = 0; m < 3; ++m) {
        int task = 3 * tid + m;
        if (task < NTOPS) {
            int g = task / NI, j = task - g * NI;
            Ag[m] = g; Aoff[m] = last_of(j) - g; Alb[m] = g * LR + j;
        } else { Ag[m] = 0; Aoff[m] = 0; Alb[m] = 0; }
    }
    // Phase C-top: tasks 3*tid+m (task = p*82 + j)
    int Cth[3], Cfb[3], Cdn[3], Cbf[3];
#pragma unroll
    for (int m = 0; m < 3; ++m) {
        int task = 3 * tid + m;
        if (task < NTOPS) {
            int p = task / NI, j = task - p * NI;
            Cth[m] = 28 - p; Cfb[m] = (27 - p) * FR + j;
            Cdn[m] = first_of(j) + p; Cbf[m] = 27 - p;
        } else { Cth[m] = 28; Cfb[m] = 0; Cdn[m] = 0; Cbf[m] = 0; }
    }
    // Phase B mapping (tid < BTH): half = i range, jq = j-quad, f0 = frame pair
    const int Bh  = (tid >= 294);
    const int Brt = tid - 294 * Bh;
    const int jq  = Brt / 14;
    const int f0  = 2 * (Brt - 14 * jq);
    const int Bi0 = Bh ? 41 : 0;
    const int Bi1 = Bh ? 82 : 41;
    __syncthreads();

    // ================= 214 full chunks =================
    for (int c = 0; c < NFULL; ++c) {
        const int t0 = 1 + CHUNK * c;
        const float* dprev = dbuf + (c & 1) * S_PAD;
        float*       dnew  = dbuf + ((c + 1) & 1) * S_PAD;
        const float* np    = nlp + t0;
        float* Lgc = Lg + (size_t)t0 * NI;

        // ---- Phase A: L chains, 3-way ILP, predicated fused loop ----
        {
            bool v0 = (3 * tid)     < NTOPS;
            bool v1 = (3 * tid + 1) < NTOPS;
            bool v2 = (3 * tid + 2) < NTOPS;
            float a0 = v0 ? dprev[Aoff[0]] : 0.0f;
            float a1 = v1 ? dprev[Aoff[1]] : 0.0f;
            float a2 = v2 ? dprev[Aoff[2]] : 0.0f;
            int kmax = Ag[0]; if (Ag[1] > kmax) kmax = Ag[1]; if (Ag[2] > kmax) kmax = Ag[2];
#pragma unroll 4
            for (int k = 0; k < kmax; ++k) {
                float v = np[k];
                if (k < Ag[0]) a0 += v;
                if (k < Ag[1]) a1 += v;
                if (k < Ag[2]) a2 += v;
            }
            if (v0) { Lbuf[Alb[0]] = a0; Lgc[3 * tid]     = a0; }
            if (v1) { Lbuf[Alb[1]] = a1; Lgc[3 * tid + 1] = a1; }
            if (v2) { Lbuf[Alb[2]] = a2; Lgc[3 * tid + 2] = a2; }
        }
        __syncthreads();

        // ---- P1: B halves (tid<588, 4j x 2f x 41i) | C-main (tid>=588) ----
        if (tid < BTH) {
            const float4* tc = (const float4*)trans_t + jq;
            const float*  L0 = Lbuf + f0 * LR;
            const float*  L1 = L0 + LR;
            float4 A0 = make_float4(-1e30f, -1e30f, -1e30f, -1e30f);
            float4 A1 = A0;
#pragma unroll 4
            for (int i = Bi0; i < Bi1; ++i) {
                float4 tv = tc[i * (TROW / 4)];
                float l0 = L0[i];
                float l1 = L1[i];
                A0.x = fmaxf(A0.x, l0 + tv.x); A0.y = fmaxf(A0.y, l0 + tv.y);
                A0.z = fmaxf(A0.z, l0 + tv.z); A0.w = fmaxf(A0.w, l0 + tv.w);
                A1.x = fmaxf(A1.x, l1 + tv.x); A1.y = fmaxf(A1.y, l1 + tv.y);
                A1.z = fmaxf(A1.z, l1 + tv.z); A1.w = fmaxf(A1.w, l1 + tv.w);
            }
            float* Ph = Pbuf + Bh * (CHUNK * FR);
            *(float4*)(Ph + f0 * FR + 4 * jq)       = A0;
            *(float4*)(Ph + (f0 + 1) * FR + 4 * jq) = A1;
        } else {
            const int base = 8 * (tid - BTH);
            int s0 = cidx[base],     s1 = cidx[base + 1];
            int s2 = cidx[base + 2], s3 = cidx[base + 3];
            int s4 = cidx[base + 4], s5 = cidx[base + 5];
            int s6 = cidx[base + 6], s7 = cidx[base + 7];
            float m0 = dprev[s0 - CHUNK], m1 = dprev[s1 - CHUNK];
            float m2 = dprev[s2 - CHUNK], m3 = dprev[s3 - CHUNK];
            float m4 = dprev[s4 - CHUNK], m5 = dprev[s5 - CHUNK];
            float m6 = dprev[s6 - CHUNK], m7 = dprev[s7 - CHUNK];
#pragma unroll
            for (int k = 0; k < CHUNK; ++k) {
                float v = np[k];
                m0 += v; m1 += v; m2 += v; m3 += v;
                m4 += v; m5 += v; m6 += v; m7 += v;
            }
            if (base     < NMAIN) dnew[s0] = m0;
            if (base + 1 < NMAIN) dnew[s1] = m1;
            if (base + 2 < NMAIN) dnew[s2] = m2;
            if (base + 3 < NMAIN) dnew[s3] = m3;
            if (base + 4 < NMAIN) dnew[s4] = m4;
            if (base + 5 < NMAIN) dnew[s5] = m5;
            if (base + 6 < NMAIN) dnew[s6] = m6;
            if (base + 7 < NMAIN) dnew[s7] = m7;
        }
        __syncthreads();

        // ---- P2: C-top — combine halves, + blp, then chain. 3-way ILP ----
        {
            const float* P0 = Pbuf;
            const float* P1 = Pbuf + CHUNK * FR;
            bool v0 = (3 * tid)     < NTOPS;
            bool v1 = (3 * tid + 1) < NTOPS;
            bool v2 = (3 * tid + 2) < NTOPS;
            float c0 = 0.0f, c1 = 0.0f, c2 = 0.0f;
            if (v0) c0 = fmaxf(P0[Cfb[0]], P1[Cfb[0]]) + blp[t0 + Cbf[0]];
            if (v1) c1 = fmaxf(P0[Cfb[1]], P1[Cfb[1]]) + blp[t0 + Cbf[1]];
            if (v2) c2 = fmaxf(P0[Cfb[2]], P1[Cfb[2]]) + blp[t0 + Cbf[2]];
            int kmin = Cth[0]; if (Cth[1] < kmin) kmin = Cth[1]; if (Cth[2] < kmin) kmin = Cth[2];
#pragma unroll 4
            for (int k = kmin; k < CHUNK; ++k) {
                float v = np[k];
                if (k >= Cth[0]) c0 += v;
                if (k >= Cth[1]) c1 += v;
                if (k >= Cth[2]) c2 += v;
            }
            if (v0) dnew[Cdn[0]] = c0;
            if (v1) dnew[Cdn[1]] = c1;
            if (v2) dnew[Cdn[2]] = c2;
        }
        __syncthreads();
    }

    // ================= tail frames t = 5993..5999 =================
    int ping = NFULL & 1;
    for (int t = 1 + CHUNK * NFULL; t < T_LEN; ++t) {
        const float* dprev = dbuf + ping * S_PAD;
        float*       dnew  = dbuf + (ping ^ 1) * S_PAD;
        if (tid < NI) {
            float lv = dprev[last_of(tid)];
            Pbuf[tid] = lv;                       // scratch
            Lg[(size_t)t * NI + tid] = lv;
        }
        __syncthreads();
        if (tid < NI) {
            float m = -1e30f;
            for (int i = 0; i < NI; ++i)
                m = fmaxf(m, Pbuf[i] + trans_t[i * TROW + tid]);
            dnew[first_of(tid)] = m + blp[t];
        } else if (tid >= 128) {
            float nb = nlp[t];
            for (int s = tid - 128; s < S_TOT; s += TPB - 128)
                if (!isf[s]) dnew[s] = dprev[s - 1] + nb;
        }
        __syncthreads();
        ping ^= 1;
    }

    // ================= final argmax (first-max = smallest s) =================
    const float* df = dbuf + ping * S_PAD;
    for (int t = tid; t < T_LEN; t += TPB) outb[t] = 0.0f;

    float bv = -INFINITY; int bs = 0x7fffffff;
    for (int s = tid; s < S_TOT; s += TPB) {
        float v = df[s];
        if (v > bv) { bv = v; bs = s; }
    }
#pragma unroll
    for (int off = 16; off; off >>= 1) {
        float ov = __shfl_xor_sync(0xffffffffu, bv, off);
        int   oi = __shfl_xor_sync(0xffffffffu, bs, off);
        if (ov > bv || (ov == bv && oi < bs)) { bv = ov; bs = oi; }
    }
    if ((tid & 31) == 0) { redv[tid >> 5] = bv; redi[tid >> 5] = bs; }
    __syncthreads();

    // ================= warp-cooperative lazy backtrace =================
    if (tid < 32) {
        bv = redv[tid]; bs = redi[tid];
#pragma unroll
        for (int off = 16; off; off >>= 1) {
            float ov = __shfl_xor_sync(0xffffffffu, bv, off);
            int   oi = __shfl_xor_sync(0xffffffffu, bs, off);
            if (ov > bv || (ov == bv && oi < bs)) { bv = ov; bs = oi; }
        }
        int lo = 0, hi = 81;
        while (lo < hi) { int mid = (lo + hi + 1) >> 1; if (first_of(mid) <= bs) lo = mid; else hi = mid - 1; }
        int j   = lo;
        int pos = bs - first_of(j);
        int t   = T_LEN - 1;
        const int lane = tid;

        while (true) {
            int te = t - pos;
            if (te < 0) break;
            if (lane == 0) {
                float x  = lg[te];
                float sg = 1.0f / (1.0f + expf(-x));
                if (sg >= 0.05f) outb[te] = 1.0f;
            }
            if (te == 0) break;
            const float* Lr = Lg + (size_t)te * NI;
            float best = -INFINITY; int bi = 0x7fffffff;
            for (int i = lane; i < NI; i += 32) {
                float cc = Lr[i] + trans_t[i * TROW + j];
                if (cc > best) { best = cc; bi = i; }
            }
#pragma unroll
            for (int off = 16; off; off >>= 1) {
                float ov = __shfl_xor_sync(0xffffffffu, best, off);
                int   oi = __shfl_xor_sync(0xffffffffu, bi,   off);
                if (ov > best || (ov == best && oi < bi)) { best = ov; bi = oi; }
            }
            j   = bi;
            pos = 27 + j;
            t   = te - 1;
        }
    }
}

extern "C" void kernel_launch(void* const* d_in, const int* in_sizes, int n_in,
                              void* d_out, int out_size)
{
    (void)in_sizes; (void)n_in; (void)out_size;
    const float* logit = (const float*)d_in[0];
    float* out = (float*)d_out;

    const size_t smem = (size_t)(TROW * TROW + 2 * S_PAD + CHUNK * LR
                                 + 2 * CHUNK * FR + 2 * T_LEN + 32) * 4
                      + 32 * 4 + (size_t)CIDX_N * 4 + S_PAD;
    cudaFuncSetAttribute(dbn_kernel,
                         cudaFuncAttributeMaxDynamicSharedMemorySize, (int)smem);
    dbn_kernel<<<BATCH, TPB, smem>>>(logit, out);
}

// round 9
// speedup vs baseline: 1.3384x; 1.1232x over previous
#include <cuda_runtime.h>
#include <math.h>
#include <stdint.h>
#include <stddef.h>

// DBN beat decoder: 2-CTA cluster per batch, j-partitioned chunked Viterbi.
// tau = 28..109 (82 tempi), S = 5617, B = 4, T = 6000.
#define NI     82
#define TROW   84       // trans_t row stride (i-major)
#define LR     85       // Lbuf row stride
#define LBSZ   (CHUNK * LR)
#define FR     84       // Pbuf row stride
#define QS     (CHUNK * FR)
#define S_TOT  5617
#define S_PAD  5632
#define T_LEN  6000
#define BATCH  4
#define TPB    1024
#define CHUNK  28
#define NFULL  214      // full chunks cover t = 1..5992
#define SPLITJ 44
#define SPLITS 2178     // first_of(44)
#define NM0    946      // main states (p>=28) in j<44
#define NM1    2375     // main states in j>=44
#define CIDXN  2384

__device__ float g_L[(size_t)BATCH * T_LEN * NI];   // exact L for lazy backtrace

__device__ __forceinline__ int first_of(int j) { return 28 * j + (j * (j - 1)) / 2; }
__device__ __forceinline__ int last_of(int j)  { return first_of(j) + 27 + j; }

__device__ __forceinline__ uint32_t smem_u32(const void* p) {
    uint32_t a;
    asm("{ .reg .u64 t; cvta.to.shared.u64 t, %1; cvt.u32.u64 %0, t; }" : "=r"(a) : "l"(p));
    return a;
}
__device__ __forceinline__ uint32_t mapa_rank(uint32_t addr, uint32_t rank) {
    uint32_t r;
    asm("mapa.shared::cluster.u32 %0, %1, %2;" : "=r"(r) : "r"(addr), "r"(rank));
    return r;
}
__device__ __forceinline__ void st_cluster(uint32_t addr, float v) {
    asm volatile("st.shared::cluster.f32 [%0], %1;" :: "r"(addr), "f"(v) : "memory");
}
#define CLUSTER_SYNC() do { \
    asm volatile("barrier.cluster.arrive.aligned;" ::: "memory"); \
    asm volatile("barrier.cluster.wait.aligned;"   ::: "memory"); } while (0)

__global__ __launch_bounds__(TPB, 1)
void dbn_kernel(const float* __restrict__ logit, float* __restrict__ out)
{
    extern __shared__ char smraw[];
    float* trans_t = (float*)smraw;                 // [84][84] trans_t[i][j]
    float* dbuf    = trans_t + TROW * TROW;         // [2][5632] delta (own partition live)
    float* Lbuf    = dbuf + 2 * S_PAD;              // [2][28][85]
    float* Pbuf    = Lbuf + 2 * LBSZ;               // [4][28][84] B partial maxes
    float* blp     = Pbuf + 4 * QS;                 // 6000
    float* nlp     = blp + T_LEN;                   // 6000
    float* redv    = nlp + T_LEN;                   // 32
    int*   redi    = (int*)(redv + 32);             // 32
    int*   cidx    = redi + 32;                     // 2384
    unsigned char* isf = (unsigned char*)(cidx + CIDXN);  // 5632

    const int tid = threadIdx.x;
    const int b   = blockIdx.x >> 1;
    uint32_t rnk;
    asm("mov.u32 %0, %%cluster_ctarank;" : "=r"(rnk));
    const int r = (int)rnk;

    const float* lg = logit + (size_t)b * T_LEN;
    float* Lg   = g_L + (size_t)b * T_LEN * NI;
    float* outb = out + (size_t)b * T_LEN;

    // per-rank partition constants
    const int JB  = r ? SPLITJ : 0;
    const int NJ  = r ? (NI - SPLITJ) : SPLITJ;     // 38 / 44
    const int QN  = r ? 10 : 11;                    // j-quads (CTA1 pads j=82,83)
    const int BTH = QN * 14 * 4;                    // 616 / 560
    const int NA  = NJ * CHUNK;                     // 1232 / 1064
    const int NM  = r ? NM1 : NM0;
    const int NC  = (NM + 7) / 8;                   // 119 / 297

    // DSMEM peer bases
    const uint32_t peerL = mapa_rank(smem_u32(Lbuf), rnk ^ 1u);
    const uint32_t peerD = mapa_rank(smem_u32(dbuf), rnk ^ 1u);

    // ================= setup =================
    if (tid < NI) {               // trans row i = tid (fp64, matches numpy)
        double ti = (double)(28 + tid);
        double sum = 0.0;
        for (int jj = 0; jj < NI; ++jj)
            sum += exp(-100.0 * fabs((double)(28 + jj) / ti - 1.0));
        double ls = log(sum);
        for (int jj = 0; jj < NI; ++jj) {
            double rr = -100.0 * fabs((double)(28 + jj) / ti - 1.0);
            trans_t[tid * TROW + jj] = (float)(rr - ls);
        }
        trans_t[tid * TROW + 82] = -1e30f;
        trans_t[tid * TROW + 83] = -1e30f;
    }
    for (int s = tid; s < S_PAD; s += TPB) isf[s] = 0;
    for (int t = tid; t < T_LEN; t += TPB) {
        float x  = lg[t];
        float l1 = log1pf(expf(-fabsf(x)));
        blp[t] = fminf(x, 0.0f) - l1;
        nlp[t] = fminf(-x, 0.0f) - l1;
    }
    // cidx: own main-state ids (p >= 28), global triangular index offset by rank
    for (int k = tid; k < 8 * NC; k += TPB) {
        if (k < NM) {
            int kk = k + (r ? NM0 : 0);
            int j = (int)((1.0 + sqrt(8.0 * (double)kk + 1.0)) * 0.5);
            while ((j * (j + 1)) / 2 <= kk) ++j;
            while ((j * (j - 1)) / 2 > kk)  --j;
            int m = kk - (j * (j - 1)) / 2;
            cidx[k] = first_of(j) + 28 + m;
        } else cidx[k] = S_PAD - 1;
    }
    __syncthreads();
    if (tid < NI) isf[first_of(tid)] = 1;
    __syncthreads();

    const float logS = logf((float)S_TOT);
    for (int s = tid; s < S_TOT; s += TPB)
        dbuf[s] = (isf[s] ? blp[0] : nlp[0]) - logS;

    // ---- per-thread chunk-invariant constants ----
    // A tasks (2/thread): task = g*NJ + q, j = JB + q
    int Ag[2], Aoff[2], Alb[2], Agn[2];
#pragma unroll
    for (int m = 0; m < 2; ++m) {
        int task = 2 * tid + m;
        if (task < NA) {
            int g = task / NJ, q = task - g * NJ, j = JB + q;
            Ag[m] = g; Aoff[m] = last_of(j) - g;
            Alb[m] = g * LR + j; Agn[m] = g * NI + j;
        } else { Ag[m] = 0; Aoff[m] = 0; Alb[m] = 0; Agn[m] = 0; }
    }
    // C-top tasks (2/thread): task = p*NJ + q
    int Cth[2], Cfb[2], Cdn[2], Cbf[2];
#pragma unroll
    for (int m = 0; m < 2; ++m) {
        int task = 2 * tid + m;
        if (task < NA) {
            int p = task / NJ, q = task - p * NJ, j = JB + q;
            Cth[m] = 28 - p; Cfb[m] = (27 - p) * FR + j;
            Cdn[m] = first_of(j) + p; Cbf[m] = 27 - p;
        } else { Cth[m] = 28; Cfb[m] = 0; Cdn[m] = 0; Cbf[m] = 0; }
    }
    // B mapping (tid < BTH): i-quarter h, j-quad jq, frame pair f0
    const int h    = tid / (QN * 14);
    const int brem = tid - h * (QN * 14);
    const int jq   = brem / 14;
    const int f0   = 2 * (brem - 14 * jq);
    const int jcol = JB + 4 * jq;
    const int Bi0  = (h == 0) ? 0 : (h == 1) ? 21 : (h == 2) ? 42 : 62;
    const int Bi1  = (h == 0) ? 21 : (h == 1) ? 42 : (h == 2) ? 62 : 82;
    __syncthreads();

    // ================= 214 full chunks =================
    for (int c = 0; c < NFULL; ++c) {
        const int t0 = 1 + CHUNK * c;
        const float* dprev = dbuf + (c & 1) * S_PAD;
        float*       dnew  = dbuf + ((c + 1) & 1) * S_PAD;
        const float* np    = nlp + t0;
        const int    lsel  = (c & 1) * LBSZ;
        float*       Lw    = Lbuf + lsel;
        const uint32_t LwP = peerL + (uint32_t)lsel * 4u;
        float* Lgc = Lg + (size_t)t0 * NI;

        // ---- A: own L chains (2-way ILP), write local + peer + global ----
        {
            bool v0 = (2 * tid)     < NA;
            bool v1 = (2 * tid + 1) < NA;
            float a0 = v0 ? dprev[Aoff[0]] : 0.0f;
            float a1 = v1 ? dprev[Aoff[1]] : 0.0f;
            int kmax = Ag[0] > Ag[1] ? Ag[0] : Ag[1];
#pragma unroll 4
            for (int k = 0; k < kmax; ++k) {
                float v = np[k];
                if (k < Ag[0]) a0 += v;
                if (k < Ag[1]) a1 += v;
            }
            if (v0) { Lw[Alb[0]] = a0; st_cluster(LwP + 4u * Alb[0], a0); Lgc[Agn[0]] = a0; }
            if (v1) { Lw[Alb[1]] = a1; st_cluster(LwP + 4u * Alb[1], a1); Lgc[Agn[1]] = a1; }
        }
        CLUSTER_SYNC();   // L complete in both CTAs (and orders local smem)

        // ---- P1: B (own j, i-quarter) | C-main (own p>=28 states) ----
        if (tid < BTH) {
            const float4* tc = (const float4*)trans_t + (jcol >> 2);
            const float*  L0 = Lbuf + lsel + f0 * LR;
            const float*  L1 = L0 + LR;
            float4 A0 = make_float4(-1e30f, -1e30f, -1e30f, -1e30f);
            float4 A1 = A0;
#pragma unroll 4
            for (int i = Bi0; i < Bi1; ++i) {
                float4 tv = tc[i * (TROW / 4)];
                float l0 = L0[i];
                float l1 = L1[i];
                A0.x = fmaxf(A0.x, l0 + tv.x); A0.y = fmaxf(A0.y, l0 + tv.y);
                A0.z = fmaxf(A0.z, l0 + tv.z); A0.w = fmaxf(A0.w, l0 + tv.w);
                A1.x = fmaxf(A1.x, l1 + tv.x); A1.y = fmaxf(A1.y, l1 + tv.y);
                A1.z = fmaxf(A1.z, l1 + tv.z); A1.w = fmaxf(A1.w, l1 + tv.w);
            }
            float* Ph = Pbuf + h * QS;
            *(float4*)(Ph + f0 * FR + jcol)       = A0;
            *(float4*)(Ph + (f0 + 1) * FR + jcol) = A1;
        } else if (tid < BTH + NC) {
            const int base = 8 * (tid - BTH);
            int s0 = cidx[base],     s1 = cidx[base + 1];
            int s2 = cidx[base + 2], s3 = cidx[base + 3];
            int s4 = cidx[base + 4], s5 = cidx[base + 5];
            int s6 = cidx[base + 6], s7 = cidx[base + 7];
            float m0 = dprev[s0 - CHUNK], m1 = dprev[s1 - CHUNK];
            float m2 = dprev[s2 - CHUNK], m3 = dprev[s3 - CHUNK];
            float m4 = dprev[s4 - CHUNK], m5 = dprev[s5 - CHUNK];
            float m6 = dprev[s6 - CHUNK], m7 = dprev[s7 - CHUNK];
#pragma unroll
            for (int k = 0; k < CHUNK; ++k) {
                float v = np[k];
                m0 += v; m1 += v; m2 += v; m3 += v;
                m4 += v; m5 += v; m6 += v; m7 += v;
            }
            if (base     < NM) dnew[s0] = m0;
            if (base + 1 < NM) dnew[s1] = m1;
            if (base + 2 < NM) dnew[s2] = m2;
            if (base + 3 < NM) dnew[s3] = m3;
            if (base + 4 < NM) dnew[s4] = m4;
            if (base + 5 < NM) dnew[s5] = m5;
            if (base + 6 < NM) dnew[s6] = m6;
            if (base + 7 < NM) dnew[s7] = m7;
        }
        __syncthreads();

        // ---- P2: C-top — combine 4 partials, + blp, chain (2-way ILP) ----
        {
            const float* P0 = Pbuf;
            const float* P1 = Pbuf + QS;
            const float* P2 = Pbuf + 2 * QS;
            const float* P3 = Pbuf + 3 * QS;
            bool v0 = (2 * tid)     < NA;
            bool v1 = (2 * tid + 1) < NA;
            float c0 = 0.0f, c1 = 0.0f;
            if (v0) c0 = fmaxf(fmaxf(P0[Cfb[0]], P1[Cfb[0]]),
                               fmaxf(P2[Cfb[0]], P3[Cfb[0]])) + blp[t0 + Cbf[0]];
            if (v1) c1 = fmaxf(fmaxf(P0[Cfb[1]], P1[Cfb[1]]),
                               fmaxf(P2[Cfb[1]], P3[Cfb[1]])) + blp[t0 + Cbf[1]];
            int kmin = Cth[0] < Cth[1] ? Cth[0] : Cth[1];
#pragma unroll 4
            for (int k = kmin; k < CHUNK; ++k) {
                float v = np[k];
                if (k >= Cth[0]) c0 += v;
                if (k >= Cth[1]) c1 += v;
            }
            if (v0) dnew[Cdn[0]] = c0;
            if (v1) dnew[Cdn[1]] = c1;
        }
        __syncthreads();
    }

    // ================= exchange final delta partitions =================
    int ping = NFULL & 1;   // buffer holding delta at t=5992
    {
        const int slo = r ? SPLITS : 0;
        const int shi = r ? S_TOT : SPLITS;
        const float* dp = dbuf + ping * S_PAD;
        const uint32_t pd = peerD + (uint32_t)(ping * S_PAD) * 4u;
        for (int s = slo + tid; s < shi; s += TPB)
            st_cluster(pd + 4u * s, dp[s]);
    }
    CLUSTER_SYNC();

    // ================= tail t = 5993..5999 (redundant, both CTAs) =========
    for (int t = 1 + CHUNK * NFULL; t < T_LEN; ++t) {
        const float* dprev = dbuf + ping * S_PAD;
        float*       dnew  = dbuf + (ping ^ 1) * S_PAD;
        if (tid < NI) {
            float lv = dprev[last_of(tid)];
            Pbuf[tid] = lv;                   // scratch
            Lg[(size_t)t * NI + tid] = lv;
        }
        __syncthreads();
        if (tid < NI) {
            float m = -1e30f;
            for (int i = 0; i < NI; ++i)
                m = fmaxf(m, Pbuf[i] + trans_t[i * TROW + tid]);
            dnew[first_of(tid)] = m + blp[t];
        } else if (tid >= 128) {
            float nb = nlp[t];
            for (int s = tid - 128; s < S_TOT; s += TPB - 128)
                if (!isf[s]) dnew[s] = dprev[s - 1] + nb;
        }
        __syncthreads();
        ping ^= 1;
    }

    // ================= final argmax (first-max = smallest s) ==============
    const float* df = dbuf + ping * S_PAD;
    if (r == 0) for (int t = tid; t < T_LEN; t += TPB) outb[t] = 0.0f;

    float bv = -INFINITY; int bs = 0x7fffffff;
    for (int s = tid; s < S_TOT; s += TPB) {
        float v = df[s];
        if (v > bv) { bv = v; bs = s; }
    }
#pragma unroll
    for (int off = 16; off; off >>= 1) {
        float ov = __shfl_xor_sync(0xffffffffu, bv, off);
        int   oi = __shfl_xor_sync(0xffffffffu, bs, off);
        if (ov > bv || (ov == bv && oi < bs)) { bv = ov; bs = oi; }
    }
    if ((tid & 31) == 0) { redv[tid >> 5] = bv; redi[tid >> 5] = bs; }
    __syncthreads();

    // ================= backtrace (rank 0, warp 0) =========================
    if (r == 0 && tid < 32) {
        bv = redv[tid]; bs = redi[tid];
#pragma unroll
        for (int off = 16; off; off >>= 1) {
            float ov = __shfl_xor_sync(0xffffffffu, bv, off);
            int   oi = __shfl_xor_sync(0xffffffffu, bs, off);
            if (ov > bv || (ov == bv && oi < bs)) { bv = ov; bs = oi; }
        }
        int lo = 0, hi = 81;
        while (lo < hi) { int mid = (lo + hi + 1) >> 1; if (first_of(mid) <= bs) lo = mid; else hi = mid - 1; }
        int j   = lo;
        int pos = bs - first_of(j);
        int t   = T_LEN - 1;
        const int lane = tid;

        while (true) {
            int te = t - pos;
            if (te < 0) break;
            if (lane == 0) {
                float x  = lg[te];
                float sg = 1.0f / (1.0f + expf(-x));
                if (sg >= 0.05f) outb[te] = 1.0f;
            }
            if (te == 0) break;
            const float* Lr = Lg + (size_t)te * NI;
            float best = -INFINITY; int bi = 0x7fffffff;
            for (int i = lane; i < NI; i += 32) {
                float cc = Lr[i] + trans_t[i * TROW + j];
                if (cc > best) { best = cc; bi = i; }
            }
#pragma unroll
            for (int off = 16; off; off >>= 1) {
                float ov = __shfl_xor_sync(0xffffffffu, best, off);
                int   oi = __shfl_xor_sync(0xffffffffu, bi,   off);
                if (ov > best || (ov == best && oi < bi)) { best = ov; bi = oi; }
            }
            j   = bi;
            pos = 27 + j;
            t   = te - 1;
        }
    }
    CLUSTER_SYNC();
}

extern "C" void kernel_launch(void* const* d_in, const int* in_sizes, int n_in,
                              void* d_out, int out_size)
{
    (void)in_sizes; (void)n_in; (void)out_size;
    const float* logit = (const float*)d_in[0];
    float* out = (float*)d_out;

    const size_t smem = (size_t)(TROW * TROW + 2 * S_PAD + 2 * LBSZ + 4 * QS
                                 + 2 * T_LEN + 64 + CIDXN) * 4 + S_PAD;
    cudaFuncSetAttribute(dbn_kernel,
                         cudaFuncAttributeMaxDynamicSharedMemorySize, (int)smem);

    cudaLaunchConfig_t cfg = {};
    cfg.gridDim  = dim3(2 * BATCH, 1, 1);
    cfg.blockDim = dim3(TPB, 1, 1);
    cfg.dynamicSmemBytes = smem;
    cfg.stream = 0;
    cudaLaunchAttribute attrs[1];
    attrs[0].id = cudaLaunchAttributeClusterDimension;
    attrs[0].val.clusterDim.x = 2;
    attrs[0].val.clusterDim.y = 1;
    attrs[0].val.clusterDim.z = 1;
    cfg.attrs = attrs;
    cfg.numAttrs = 1;
    cudaLaunchKernelEx(&cfg, dbn_kernel, logit, out);
}